// round 5
// baseline (speedup 1.0000x reference)
#include <cuda_runtime.h>
#include <cuda_bf16.h>

// Shapes (fixed by problem)
#define Bb 32
#define Nn 32
#define Ll 512
#define Mm 64
#define Ff 64
#define EPSV 1e-8f

// Scratch (no cudaMalloc allowed): alpha [N,L,M] f32 (4MB) + reciprocal denom [N,M]
__device__ float g_alpha[Nn * Ll * Mm];
__device__ float g_rdenom[Nn * Mm];

// ---------------------------------------------------------------------------
// Kernel 1: alpha[n,l,m] = sigmoid((tr-t)/k) * sigmoid((t-tl)/k), k=softplus(kappa[n])
// grid (8, 32) blocks of 256 threads: block = (l-chunk of 64, n)
// ---------------------------------------------------------------------------
__global__ void __launch_bounds__(256) alpha_kernel(
    const float* __restrict__ t,       // [L,1]
    const float* __restrict__ t_left,  // [N,M]
    const float* __restrict__ t_right, // [N,M]
    const float* __restrict__ kappa)   // [N,1]
{
    const int n  = blockIdx.y;
    const int l0 = blockIdx.x * 64;
    const int tid = threadIdx.x;
    const int m  = tid & 63;
    const int ls = tid >> 6;  // 0..3

    const float ka = kappa[n];
    const float k  = (ka > 20.0f) ? ka : log1pf(expf(ka));
    const float invk = 1.0f / k;
    const float tlv = t_left [n * Mm + m];
    const float trv = t_right[n * Mm + m];

#pragma unroll
    for (int j = 0; j < 16; j++) {
        const int l = l0 + ls + j * 4;
        const float tv = t[l];
        const float z1 = (trv - tv) * invk;
        const float z2 = (tv - tlv) * invk;
        const float s1 = 1.0f / (1.0f + expf(-z1));
        const float s2 = 1.0f / (1.0f + expf(-z2));
        g_alpha[(n * Ll + l) * Mm + m] = s1 * s2;
    }
}

// ---------------------------------------------------------------------------
// Kernel 2: rdenom[n,m] = 1 / (sum_l alpha[n,l,m] + EPS)
// grid 32 blocks of 256 threads
// ---------------------------------------------------------------------------
__global__ void __launch_bounds__(256) denom_kernel()
{
    const int n = blockIdx.x;
    const int tid = threadIdx.x;
    const int m  = tid & 63;
    const int ls = tid >> 6;

    float s = 0.0f;
#pragma unroll 8
    for (int l = ls; l < Ll; l += 4)
        s += g_alpha[(n * Ll + l) * Mm + m];

    __shared__ float red[256];
    red[tid] = s;
    __syncthreads();
    if (ls == 0) {
        const float tot = red[m] + red[m + 64] + red[m + 128] + red[m + 192];
        g_rdenom[n * Mm + m] = 1.0f / (tot + EPSV);
    }
}

// ---------------------------------------------------------------------------
// Kernel 3: out[b,n,m,f] = (sum_l alpha[n,l,m] * x[b,n,l,f]) * rdenom[n,m]
// One CTA per (b,n). 256 threads, each computes a 4(m) x 4(f) micro-tile.
// Packed f32x2 FFMA (2 FMA/instr) with alpha pre-duplicated in smem.
// ---------------------------------------------------------------------------
__device__ __forceinline__ unsigned long long dup2(float v) {
    const unsigned int b = __float_as_uint(v);
    return ((unsigned long long)b << 32) | (unsigned long long)b;
}

#define FFMA2(d, a, b) \
    asm("fma.rn.f32x2 %0, %1, %2, %0;" : "+l"(d) : "l"(a), "l"(b))

__global__ void __launch_bounds__(256) gemm_kernel(
    const float* __restrict__ x,   // [B,N,L,F]
    float* __restrict__ out)       // [B,N,M,F]
{
    const int b = blockIdx.x;
    const int n = blockIdx.y;

    __shared__ unsigned long long As[32 * Mm];  // alpha, each value duplicated (a,a)
    __shared__ float Xs[32 * Ff];

    const int tid = threadIdx.x;
    const int tx = tid & 15;   // f tile index
    const int ty = tid >> 4;   // m tile index
    const int m0 = ty * 4;
    const int f0 = tx * 4;

    // loader mapping: 16 rows x 16 col-groups per pass, 2 passes for 32 rows
    const int lrow = tid >> 4;
    const int lcol = (tid & 15) * 4;

    const float* __restrict__ xg = x + (size_t)((b * Nn + n) * Ll) * Ff;
    const float* __restrict__ ag = g_alpha + (size_t)(n * Ll) * Mm;

    unsigned long long acc[4][2];
#pragma unroll
    for (int i = 0; i < 4; i++) { acc[i][0] = 0ull; acc[i][1] = 0ull; }

    for (int l0 = 0; l0 < Ll; l0 += 32) {
#pragma unroll
        for (int r = 0; r < 2; r++) {
            const int row = lrow + r * 16;
            const float4 xv = *(const float4*)(xg + (l0 + row) * Ff + lcol);
            *(float4*)&Xs[row * Ff + lcol] = xv;
            const float4 av = *(const float4*)(ag + (l0 + row) * Mm + lcol);
            As[row * Mm + lcol + 0] = dup2(av.x);
            As[row * Mm + lcol + 1] = dup2(av.y);
            As[row * Mm + lcol + 2] = dup2(av.z);
            As[row * Mm + lcol + 3] = dup2(av.w);
        }
        __syncthreads();

#pragma unroll
        for (int kk = 0; kk < 32; kk++) {
            const ulonglong2 a01 = *(const ulonglong2*)&As[kk * Mm + m0];
            const ulonglong2 a23 = *(const ulonglong2*)&As[kk * Mm + m0 + 2];
            const ulonglong2 xv  = *(const ulonglong2*)&Xs[kk * Ff + f0];
            FFMA2(acc[0][0], a01.x, xv.x);
            FFMA2(acc[0][1], a01.x, xv.y);
            FFMA2(acc[1][0], a01.y, xv.x);
            FFMA2(acc[1][1], a01.y, xv.y);
            FFMA2(acc[2][0], a23.x, xv.x);
            FFMA2(acc[2][1], a23.x, xv.y);
            FFMA2(acc[3][0], a23.y, xv.x);
            FFMA2(acc[3][1], a23.y, xv.y);
        }
        __syncthreads();
    }

    // Epilogue: multiply by reciprocal denominator, store 4 float4 rows
    float* __restrict__ og = out + (size_t)((b * Nn + n) * Mm) * Ff;
#pragma unroll
    for (int mi = 0; mi < 4; mi++) {
        const float rd = g_rdenom[n * Mm + m0 + mi];
        float4 o;
        o.x = __uint_as_float((unsigned int)(acc[mi][0]       )) * rd;
        o.y = __uint_as_float((unsigned int)(acc[mi][0] >> 32 )) * rd;
        o.z = __uint_as_float((unsigned int)(acc[mi][1]       )) * rd;
        o.w = __uint_as_float((unsigned int)(acc[mi][1] >> 32 )) * rd;
        *(float4*)&og[(m0 + mi) * Ff + f0] = o;
    }
}

// ---------------------------------------------------------------------------
// Launch: alpha -> denom -> gemm (sequential on default stream, capturable)
// Inputs (metadata order): x_aug, t, t_left, t_right, kappa
// ---------------------------------------------------------------------------
extern "C" void kernel_launch(void* const* d_in, const int* in_sizes, int n_in,
                              void* d_out, int out_size)
{
    (void)in_sizes; (void)n_in; (void)out_size;
    const float* x       = (const float*)d_in[0];
    const float* t       = (const float*)d_in[1];
    const float* t_left  = (const float*)d_in[2];
    const float* t_right = (const float*)d_in[3];
    const float* kappa   = (const float*)d_in[4];
    float* out = (float*)d_out;

    alpha_kernel<<<dim3(Ll / 64, Nn), 256>>>(t, t_left, t_right, kappa);
    denom_kernel<<<Nn, 256>>>();
    gemm_kernel<<<dim3(Bb, Nn), 256>>>(x, out);
}

// round 6
// speedup vs baseline: 1.3632x; 1.3632x over previous
#include <cuda_runtime.h>
#include <cuda_bf16.h>

// Shapes (fixed by problem)
#define Bb 32
#define Nn 32
#define Ll 512
#define Mm 64
#define Ff 64
#define EPSV 1e-8f

// Scratch (no cudaMalloc allowed):
// alpha stored PRE-DUPLICATED as float2 (a,a) so the gemm can cp.async it
// straight into smem and feed fma.rn.f32x2 without any packing.
__device__ float2 g_alpha_dup[Nn * Ll * Mm];   // 8 MB
__device__ float  g_rdenom[Nn * Mm];

// ---------------------------------------------------------------------------
// Kernel 1: alpha[n,l,m] = sigmoid((tr-t)/k) * sigmoid((t-tl)/k), k=softplus(kappa)
// Fast-math sigmoid (MUFU path). grid (8, 32) x 256 threads.
// ---------------------------------------------------------------------------
__global__ void __launch_bounds__(256) alpha_kernel(
    const float* __restrict__ t,       // [L,1]
    const float* __restrict__ t_left,  // [N,M]
    const float* __restrict__ t_right, // [N,M]
    const float* __restrict__ kappa)   // [N,1]
{
    const int n  = blockIdx.y;
    const int l0 = blockIdx.x * 64;
    const int tid = threadIdx.x;
    const int m  = tid & 63;
    const int ls = tid >> 6;  // 0..3

    const float ka = kappa[n];
    const float k  = (ka > 20.0f) ? ka : log1pf(expf(ka));   // per-n, cheap, keep precise
    const float invk = 1.0f / k;
    const float tlv = t_left [n * Mm + m];
    const float trv = t_right[n * Mm + m];

#pragma unroll
    for (int j = 0; j < 16; j++) {
        const int l = l0 + ls + j * 4;
        const float tv = t[l];
        const float e1 = __expf((tv - trv) * invk);   // exp(-z1)
        const float e2 = __expf((tlv - tv) * invk);   // exp(-z2)
        const float s1 = __fdividef(1.0f, 1.0f + e1);
        const float s2 = __fdividef(1.0f, 1.0f + e2);
        const float a  = s1 * s2;
        g_alpha_dup[(n * Ll + l) * Mm + m] = make_float2(a, a);
    }
}

// ---------------------------------------------------------------------------
// Kernel 2: rdenom[n,m] = 1 / (sum_l alpha[n,l,m] + EPS)
// ---------------------------------------------------------------------------
__global__ void __launch_bounds__(256) denom_kernel()
{
    const int n = blockIdx.x;
    const int tid = threadIdx.x;
    const int m  = tid & 63;
    const int ls = tid >> 6;

    float s = 0.0f;
#pragma unroll 8
    for (int l = ls; l < Ll; l += 4)
        s += g_alpha_dup[(n * Ll + l) * Mm + m].x;

    __shared__ float red[256];
    red[tid] = s;
    __syncthreads();
    if (ls == 0) {
        const float tot = red[m] + red[m + 64] + red[m + 128] + red[m + 192];
        g_rdenom[n * Mm + m] = 1.0f / (tot + EPSV);
    }
}

// ---------------------------------------------------------------------------
// Kernel 3: out[b,n,m,f] = (sum_l alpha[n,l,m] * x[b,n,l,f]) * rdenom[n,m]
// One CTA per (b,n), 128 threads. Each thread: 4(m) x 8(f) micro-tile.
// 2-stage cp.async pipeline; packed f32x2 FFMA; 16 FFMA2 per 4 LDS.128.
// ---------------------------------------------------------------------------
#define FFMA2(d, a, b) \
    asm("fma.rn.f32x2 %0, %1, %2, %0;" : "+l"(d) : "l"(a), "l"(b))

#define CP_ASYNC16(dst, src) \
    asm volatile("cp.async.cg.shared.global [%0], [%1], 16;" :: "r"(dst), "l"(src))
#define CP_COMMIT() asm volatile("cp.async.commit_group;")
#define CP_WAIT(N)  asm volatile("cp.async.wait_group %0;" :: "n"(N))

typedef unsigned long long ull;

__global__ void __launch_bounds__(128) gemm_kernel(
    const float* __restrict__ x,   // [B,N,L,F]
    float* __restrict__ out)       // [B,N,M,F]
{
    const int b = blockIdx.x;
    const int n = blockIdx.y;

    __shared__ ull   As[2][32 * Mm];   // 2 x 16 KB, dup alpha pairs
    __shared__ float Xs[2][32 * Ff];   // 2 x 8 KB

    const int tid = threadIdx.x;
    const int m0 = (tid >> 3) * 4;     // 0,4,...,60
    const int f0 = (tid & 7)  * 8;     // 0,8,...,56

    const char* __restrict__ xg =
        (const char*)(x + (size_t)((b * Nn + n) * Ll) * Ff);
    const char* __restrict__ ag =
        (const char*)(g_alpha_dup + (size_t)(n * Ll) * Mm);

    const unsigned int sA0 = (unsigned int)__cvta_generic_to_shared(&As[0][0]);
    const unsigned int sA1 = (unsigned int)__cvta_generic_to_shared(&As[1][0]);
    const unsigned int sX0 = (unsigned int)__cvta_generic_to_shared(&Xs[0][0]);
    const unsigned int sX1 = (unsigned int)__cvta_generic_to_shared(&Xs[1][0]);

    // Prefetch one chunk (32 l-rows): As chunk = 16384 B, Xs chunk = 8192 B.
    // 128 threads: 8 x 16B for As, 4 x 16B for Xs.
    auto prefetch = [&](int chunk, int st) {
        const unsigned int dA = st ? sA1 : sA0;
        const unsigned int dX = st ? sX1 : sX0;
        const char* srcA = ag + (size_t)chunk * 16384;
        const char* srcX = xg + (size_t)chunk * 8192;
#pragma unroll
        for (int i = 0; i < 8; i++) {
            const int off = (tid + i * 128) * 16;
            CP_ASYNC16(dA + off, srcA + off);
        }
#pragma unroll
        for (int i = 0; i < 4; i++) {
            const int off = (tid + i * 128) * 16;
            CP_ASYNC16(dX + off, srcX + off);
        }
        CP_COMMIT();
    };

    ull acc[4][4];
#pragma unroll
    for (int i = 0; i < 4; i++)
#pragma unroll
        for (int j = 0; j < 4; j++) acc[i][j] = 0ull;

    prefetch(0, 0);

    for (int chunk = 0; chunk < 16; chunk++) {
        const int st = chunk & 1;
        if (chunk + 1 < 16) {
            prefetch(chunk + 1, st ^ 1);
            CP_WAIT(1);            // current chunk's group complete
        } else {
            CP_WAIT(0);
        }
        __syncthreads();

        const ull*   Ab = &As[st][0];
        const float* Xb = &Xs[st][0];
#pragma unroll 8
        for (int kk = 0; kk < 32; kk++) {
            const ulonglong2 a01 = *(const ulonglong2*)(Ab + kk * Mm + m0);
            const ulonglong2 a23 = *(const ulonglong2*)(Ab + kk * Mm + m0 + 2);
            const ulonglong2 x01 = *(const ulonglong2*)(Xb + kk * Ff + f0);
            const ulonglong2 x23 = *(const ulonglong2*)(Xb + kk * Ff + f0 + 4);

            FFMA2(acc[0][0], a01.x, x01.x);
            FFMA2(acc[0][1], a01.x, x01.y);
            FFMA2(acc[0][2], a01.x, x23.x);
            FFMA2(acc[0][3], a01.x, x23.y);
            FFMA2(acc[1][0], a01.y, x01.x);
            FFMA2(acc[1][1], a01.y, x01.y);
            FFMA2(acc[1][2], a01.y, x23.x);
            FFMA2(acc[1][3], a01.y, x23.y);
            FFMA2(acc[2][0], a23.x, x01.x);
            FFMA2(acc[2][1], a23.x, x01.y);
            FFMA2(acc[2][2], a23.x, x23.x);
            FFMA2(acc[2][3], a23.x, x23.y);
            FFMA2(acc[3][0], a23.y, x01.x);
            FFMA2(acc[3][1], a23.y, x01.y);
            FFMA2(acc[3][2], a23.y, x23.x);
            FFMA2(acc[3][3], a23.y, x23.y);
        }
        __syncthreads();
    }

    // Epilogue: scale by reciprocal denominator, store 4 rows x 8 f
    float* __restrict__ og = out + (size_t)((b * Nn + n) * Mm) * Ff;
#pragma unroll
    for (int mi = 0; mi < 4; mi++) {
        const float rd = g_rdenom[n * Mm + m0 + mi];
        float4 o0, o1;
        o0.x = __uint_as_float((unsigned int)(acc[mi][0]      )) * rd;
        o0.y = __uint_as_float((unsigned int)(acc[mi][0] >> 32)) * rd;
        o0.z = __uint_as_float((unsigned int)(acc[mi][1]      )) * rd;
        o0.w = __uint_as_float((unsigned int)(acc[mi][1] >> 32)) * rd;
        o1.x = __uint_as_float((unsigned int)(acc[mi][2]      )) * rd;
        o1.y = __uint_as_float((unsigned int)(acc[mi][2] >> 32)) * rd;
        o1.z = __uint_as_float((unsigned int)(acc[mi][3]      )) * rd;
        o1.w = __uint_as_float((unsigned int)(acc[mi][3] >> 32)) * rd;
        *(float4*)&og[(m0 + mi) * Ff + f0]     = o0;
        *(float4*)&og[(m0 + mi) * Ff + f0 + 4] = o1;
    }
}

// ---------------------------------------------------------------------------
// Launch: alpha -> denom -> gemm (sequential, graph-capturable)
// Inputs (metadata order): x_aug, t, t_left, t_right, kappa
// ---------------------------------------------------------------------------
extern "C" void kernel_launch(void* const* d_in, const int* in_sizes, int n_in,
                              void* d_out, int out_size)
{
    (void)in_sizes; (void)n_in; (void)out_size;
    const float* x       = (const float*)d_in[0];
    const float* t       = (const float*)d_in[1];
    const float* t_left  = (const float*)d_in[2];
    const float* t_right = (const float*)d_in[3];
    const float* kappa   = (const float*)d_in[4];
    float* out = (float*)d_out;

    alpha_kernel<<<dim3(Ll / 64, Nn), 256>>>(t, t_left, t_right, kappa);
    denom_kernel<<<Nn, 256>>>();
    gemm_kernel<<<dim3(Bb, Nn), 128>>>(x, out);
}